// round 2
// baseline (speedup 1.0000x reference)
#include <cuda_runtime.h>
#include <math.h>

#define BATCH   8
#define INCH    32
#define OUTCH   32
#define TLEN    4096
#define NP      128            // conjugate pairs (state dim 256 -> 128 pairs)
#define SUB     32             // scan sub-chunk length
#define NSUB    (TLEN / SUB)   // 128 per batch
#define TILE    64             // t-tile per block (2 sub-chunks)
#define NTILE   (TLEN / TILE)  // 64

typedef unsigned long long ull;

// ---- device scratch (no allocations allowed) ----
__device__ float g_Ar[NP], g_Ai[NP], g_fr[NP], g_fi[NP], g_ALr[NP], g_ALi[NP];
__device__ float g_w[BATCH * TLEN * NP];                       // 16 MB, [b][sub][p][t32]
__device__ float g_endr[BATCH * NSUB * NP], g_endi[BATCH * NSUB * NP];
__device__ float g_sr[BATCH * NSUB * NP],  g_si[BATCH * NSUB * NP];

// ---- packed f32x2 helpers ----------------------------------------------
__device__ __forceinline__ ull pack2(float lo, float hi) {
    ull r; asm("mov.b64 %0, {%1, %2};" : "=l"(r) : "f"(lo), "f"(hi)); return r;
}
__device__ __forceinline__ void unpack2(ull v, float& lo, float& hi) {
    asm("mov.b64 {%0, %1}, %2;" : "=f"(lo), "=f"(hi) : "l"(v));
}
__device__ __forceinline__ ull fma2(ull a, ull b, ull c) {
    ull d; asm("fma.rn.f32x2 %0, %1, %2, %3;" : "=l"(d) : "l"(a), "l"(b), "l"(c));
    return d;
}

// ---- K1: per-pair parameters -------------------------------------------
__global__ void k_params(const float* __restrict__ raw_lambda,
                         const float* __restrict__ raw_omega) {
    int p = threadIdx.x;
    if (p >= NP) return;
    float x  = raw_lambda[p];
    float sp = fmaxf(x, 0.f) + log1pf(expf(-fabsf(x)));   // softplus
    float lr = -sp;
    float li = raw_omega[p];
    float er = expf(lr);
    float Ar = er * cosf(li);
    float Ai = er * sinf(li);
    float m2 = lr * lr + li * li;
    float fr, fi;
    if (sqrtf(m2) > 1e-6f) {
        float nr = Ar - 1.f, ni = Ai;
        fr = (nr * lr + ni * li) / m2;
        fi = (ni * lr - nr * li) / m2;
    } else {
        fr = 1.0f; fi = 0.f;                               // DT = 1
    }
    g_Ar[p] = Ar; g_Ai[p] = Ai; g_fr[p] = fr; g_fi[p] = fi;
    float eL = expf(lr * (float)SUB);                      // A^SUB for the scan
    g_ALr[p] = eL * cosf(li * (float)SUB);
    g_ALi[p] = eL * sinf(li * (float)SUB);
}

// ---- K2: w = Bc^T u (f32x2 GEMM) + in-register local recurrence ---------
__global__ __launch_bounds__(256) void k_chunk(const float* __restrict__ u,
                                               const float* __restrict__ Bc) {
    __shared__ float u_sm[INCH * TILE];    // [i][t]  8 KB
    int c = blockIdx.x, b = blockIdx.y;
    int t0 = c * TILE;
    int tid = threadIdx.x;

    for (int idx = tid; idx < INCH * TILE; idx += 256) {
        int i = idx >> 6, t = idx & 63;
        u_sm[idx] = u[(b * INCH + i) * TLEN + t0 + t];
    }
    __syncthreads();

    int p = tid & 127, sub = tid >> 7;     // thread owns (p, 32 contiguous t)
    ull acc[16];
#pragma unroll
    for (int j = 0; j < 16; j++) acc[j] = 0ull;

#pragma unroll 8
    for (int i = 0; i < INCH; i++) {
        float bb = __ldg(&Bc[i * NP + p]);                  // coalesced across lanes
        ull bb2 = pack2(bb, bb);
        const ulonglong2* ur = (const ulonglong2*)&u_sm[i * TILE + sub * SUB];
#pragma unroll
        for (int q = 0; q < 8; q++) {                       // LDS.128 broadcast
            ulonglong2 v = ur[q];
            acc[2 * q]     = fma2(bb2, v.x, acc[2 * q]);
            acc[2 * q + 1] = fma2(bb2, v.y, acc[2 * q + 1]);
        }
    }

    // store w, thread-contiguous layout -> fully coalesced v2.u64 stores
    int gsub = c * 2 + sub;
    size_t wb = ((size_t)(b * NSUB + gsub) * NP + p) * SUB;
    ulonglong2* wp = (ulonglong2*)&g_w[wb];
#pragma unroll
    for (int q = 0; q < 8; q++) {
        ulonglong2 v; v.x = acc[2 * q]; v.y = acc[2 * q + 1];
        wp[q] = v;
    }

    // local recurrence over own registers, zero init -> end state
    float Ar = g_Ar[p], Ai = g_Ai[p], fr = g_fr[p], fi = g_fi[p];
    float xr = 0.f, xi = 0.f;
#pragma unroll
    for (int j = 0; j < 16; j++) {
        float w0, w1; unpack2(acc[j], w0, w1);
        float nr = fmaf(Ar, xr, fmaf(-Ai, xi, fr * w0));
        float ni = fmaf(Ai, xr, fmaf( Ar, xi, fi * w0));
        xr = fmaf(Ar, nr, fmaf(-Ai, ni, fr * w1));
        xi = fmaf(Ai, nr, fmaf( Ar, ni, fi * w1));
    }
    int o = (b * NSUB + gsub) * NP + p;
    g_endr[o] = xr; g_endi[o] = xi;
}

// ---- K3: exact inter-sub-chunk scan: s[c+1] = A^SUB s[c] + end[c] -------
__global__ void k_scan() {
    int b = blockIdx.x;           // 8 blocks x 128 threads
    int p = threadIdx.x;
    float ALr = g_ALr[p], ALi = g_ALi[p];
    float xr = 0.f, xi = 0.f;
#pragma unroll 8
    for (int c = 0; c < NSUB; c++) {
        int o = (b * NSUB + c) * NP + p;
        g_sr[o] = xr; g_si[o] = xi;
        float er = g_endr[o], ei = g_endi[o];
        float nr = fmaf(ALr, xr, fmaf(-ALi, xi, er));
        float ni = fmaf(ALi, xr, fmaf( ALr, xi, ei));
        xr = nr; xi = ni;
    }
}

// ---- K4: recurrence from scan state + y = 2 C^T Re(x) (f32x2 GEMM) ------
#define XPAD 68
__global__ __launch_bounds__(256) void k_out(const float* __restrict__ C,
                                             float* __restrict__ y) {
    __shared__ float x_sm[NP * XPAD];        // [p][t] pad; 34.8 KB
    __shared__ float y_sm[TILE * 33];        // transpose pad; 8.4 KB
    int c = blockIdx.x, b = blockIdx.y;
    int tid = threadIdx.x;

    // --- load w block (contiguous, coalesced), recurrence in registers ---
    {
        int p = tid & 127, sub = tid >> 7;
        int gsub = c * 2 + sub;
        size_t wb = ((size_t)(b * NSUB + gsub) * NP + p) * SUB;
        const ulonglong2* wp = (const ulonglong2*)&g_w[wb];
        ull wr[16];
#pragma unroll
        for (int q = 0; q < 8; q++) {
            ulonglong2 v = wp[q];
            wr[2 * q] = v.x; wr[2 * q + 1] = v.y;
        }
        float Ar = g_Ar[p], Ai = g_Ai[p], fr = g_fr[p], fi = g_fi[p];
        int so = (b * NSUB + gsub) * NP + p;
        float xr = g_sr[so], xi = g_si[so];
        float xl[SUB];
#pragma unroll
        for (int j = 0; j < 16; j++) {
            float w0, w1; unpack2(wr[j], w0, w1);
            float nr = fmaf(Ar, xr, fmaf(-Ai, xi, fr * w0));
            float ni = fmaf(Ai, xr, fmaf( Ar, xi, fi * w0));
            xl[2 * j] = nr;
            xr = fmaf(Ar, nr, fmaf(-Ai, ni, fr * w1));
            xi = fmaf(Ai, nr, fmaf( Ar, ni, fi * w1));
            xl[2 * j + 1] = xr;
        }
        float* row = &x_sm[p * XPAD + sub * SUB];
#pragma unroll
        for (int q = 0; q < 8; q++)
            *(float4*)&row[4 * q] =
                make_float4(xl[4 * q], xl[4 * q + 1], xl[4 * q + 2], xl[4 * q + 3]);
    }
    __syncthreads();

    // --- GEMM: warp = 8 t's, lane = o; x loads are pure broadcast --------
    int o = tid & 31, tg = tid >> 5;
    ull acc[4] = {0ull, 0ull, 0ull, 0ull};
#pragma unroll 8
    for (int p = 0; p < NP; p++) {
        float cc = __ldg(&C[p * OUTCH + o]);                 // L1-resident
        ull cc2 = pack2(cc, cc);
        const float* xrow = &x_sm[p * XPAD + tg * 8];
        ulonglong2 v0 = *(const ulonglong2*)&xrow[0];
        ulonglong2 v1 = *(const ulonglong2*)&xrow[4];
        acc[0] = fma2(cc2, v0.x, acc[0]);
        acc[1] = fma2(cc2, v0.y, acc[1]);
        acc[2] = fma2(cc2, v1.x, acc[2]);
        acc[3] = fma2(cc2, v1.y, acc[3]);
    }
#pragma unroll
    for (int q = 0; q < 4; q++) {
        float a0, a1; unpack2(acc[q], a0, a1);
        int t = tg * 8 + 2 * q;
        y_sm[t * 33 + o]       = 2.f * a0;
        y_sm[(t + 1) * 33 + o] = 2.f * a1;
    }
    __syncthreads();

    // --- coalesced y write via smem transpose ---
    int t0 = c * TILE;
    for (int idx = tid; idx < OUTCH * TILE; idx += 256) {
        int oo = idx >> 6, t = idx & 63;
        y[(b * OUTCH + oo) * TLEN + t0 + t] = y_sm[t * 33 + oo];
    }
}

extern "C" void kernel_launch(void* const* d_in, const int* in_sizes, int n_in,
                              void* d_out, int out_size) {
    const float* u  = (const float*)d_in[0];
    const float* rl = (const float*)d_in[1];
    const float* ro = (const float*)d_in[2];
    const float* Bc = (const float*)d_in[3];   // (32, 128)
    const float* C  = (const float*)d_in[4];   // (128, 32)
    float* y = (float*)d_out;

    k_params<<<1, 128>>>(rl, ro);
    k_chunk<<<dim3(NTILE, BATCH), 256>>>(u, Bc);
    k_scan<<<BATCH, 128>>>();
    k_out<<<dim3(NTILE, BATCH), 256>>>(C, y);
}